// round 14
// baseline (speedup 1.0000x reference)
#include <cuda_runtime.h>
#include <cstdint>

#define TOT    400000
#define NPTS   50000
#define NBLK   5
#define PTS    128          // points per CTA
#define THR    128          // threads per CTA
#define XSTR   68           // activation row stride (floats)

typedef unsigned long long ull;

// Per-batch conditioning: cond[b][i][h] = task_feature[b] @ fc_c_W[i][64:576,:] + fc_c_b[i]
__device__ float g_cond[8 * NBLK * 64];

// ---------- packed f32x2 helpers ----------
__device__ __forceinline__ ull dup2(float x) {
    ull r; asm("mov.b64 %0, {%1, %1};" : "=l"(r) : "f"(x)); return r;
}
__device__ __forceinline__ float2 unpk(ull a) {
    float2 f; asm("mov.b64 {%0, %1}, %2;" : "=f"(f.x), "=f"(f.y) : "l"(a)); return f;
}
__device__ __forceinline__ void fma2(ull &a, ull x, ull w) {
    asm("fma.rn.f32x2 %0, %1, %2, %0;" : "+l"(a) : "l"(x), "l"(w));
}
__device__ __forceinline__ void add2(ull &a, ull b) {
    asm("add.rn.f32x2 %0, %0, %1;" : "+l"(a) : "l"(b));
}

// ---------- cp.async helpers ----------
__device__ __forceinline__ void cpa16(uint32_t dst, const float* src) {
    asm volatile("cp.async.cg.shared.global [%0], [%1], 16;" :: "r"(dst), "l"(src));
}
__device__ __forceinline__ void cpa_commit() {
    asm volatile("cp.async.commit_group;");
}
template<int N> __device__ __forceinline__ void cpa_wait() {
    asm volatile("cp.async.wait_group %0;" :: "n"(N));
}

// 16KB weight tile (64x64 f32): 8 x 16B per thread (128 threads)
__device__ __forceinline__ void load_w16(float* dst, const float* src, int tid) {
    uint32_t d = (uint32_t)__cvta_generic_to_shared(dst);
    #pragma unroll
    for (int t = 0; t < 8; t++) {
        int w = tid + t * THR;
        cpa16(d + w * 16, src + w * 4);
    }
}
// 32KB codes -> X (128 rows x XSTR): 16 x 16B per thread
__device__ __forceinline__ void load_codes(float* X, const float* src, int tid) {
    uint32_t d = (uint32_t)__cvta_generic_to_shared(X);
    #pragma unroll
    for (int t = 0; t < 16; t++) {
        int w = tid + t * THR;
        int pt = w >> 4, e = w & 15;
        cpa16(d + (pt * XSTR + e * 4) * 4, src + w * 4);
    }
}

// ---------- shared layout (float offsets) ----------
#define OFF_WA    0        // 4096
#define OFF_WB    4096     // 4096
#define OFF_NET   8192     // 128*68 = 8704
#define OFF_X     16896    // 8704 (codes OR relu(h))
#define OFF_OW    25600    // 768
#define OFF_OB    26368    // 16 (12 + pad)
#define OFF_PW    26384    // 192
#define OFF_PB    26576    // 64
#define OFF_CND   26640    // 2 * 320 (cond rows for this CTA's <=2 batches)
#define OFF_B0    27280    // 5*64
#define OFF_B1    27600    // 5*64
#define SM_FLOATS 27920
#define SM_BYTES  (SM_FLOATS * 4)   // 111680 B -> 2 CTAs/SM

// ---------- conditioning precompute ----------
__global__ void cond_kernel(const float* __restrict__ tf,
                            const float* __restrict__ fc_c_W,
                            const float* __restrict__ fc_c_b) {
    int bi = blockIdx.x;          // b*5 + i
    int b  = bi / NBLK, i = bi % NBLK;
    int h  = threadIdx.x & 63, g = threadIdx.x >> 6;
    const float* W = fc_c_W + (size_t)i * 576 * 64 + 64 * 64 + h;
    const float* t = tf + b * 512;
    float acc = 0.f;
    int k0 = g * 128;
    #pragma unroll 8
    for (int k = k0; k < k0 + 128; k++) acc += t[k] * W[(size_t)k * 64];
    __shared__ float red[256];
    red[threadIdx.x] = acc;
    __syncthreads();
    if (g == 0) {
        float s = red[h] + red[h + 64] + red[h + 128] + red[h + 192] + fc_c_b[i * 64 + h];
        g_cond[bi * 64 + h] = s;
    }
}

// GEMM microtile: 8 points (rows pg+16q) x 8 cols ({og*4..+3}, {32+og*4..+3}).
// x double-buffered one kk-chunk ahead; FMAs ordered j-OUTER / q-INNER so the
// weight operand repeats in 8 consecutive FFMA2s -> operand-reuse cache hit
// -> RF banking rt=2 instead of rt=3.
__device__ __forceinline__ void mm64(ull acc[8][4], const float* __restrict__ xb,
                                     const float* __restrict__ Wt, bool relu_x) {
    float xa[2][8][4];
    #pragma unroll
    for (int q = 0; q < 8; q++)
        *(float4*)xa[0][q] = *(const float4*)(xb + q * 16 * XSTR);
    #pragma unroll 2
    for (int kc = 0; kc < 16; kc++) {
        const int cur = kc & 1, nxt = cur ^ 1;
        if (kc < 15) {
            #pragma unroll
            for (int q = 0; q < 8; q++)
                *(float4*)xa[nxt][q] = *(const float4*)(xb + q * 16 * XSTR + (kc + 1) * 4);
        }
        #pragma unroll
        for (int d = 0; d < 4; d++) {
            ulonglong2 wA = *(const ulonglong2*)(Wt + (kc * 4 + d) * 64);
            ulonglong2 wB = *(const ulonglong2*)(Wt + (kc * 4 + d) * 64 + 32);
            ull xd[8];
            #pragma unroll
            for (int q = 0; q < 8; q++) {
                float xv = xa[cur][q][d];
                if (relu_x) xv = fmaxf(xv, 0.f);
                xd[q] = dup2(xv);
            }
            #pragma unroll
            for (int q = 0; q < 8; q++) fma2(acc[q][0], xd[q], wA.x);
            #pragma unroll
            for (int q = 0; q < 8; q++) fma2(acc[q][1], xd[q], wA.y);
            #pragma unroll
            for (int q = 0; q < 8; q++) fma2(acc[q][2], xd[q], wB.x);
            #pragma unroll
            for (int q = 0; q < 8; q++) fma2(acc[q][3], xd[q], wB.y);
        }
    }
}

__global__ __launch_bounds__(THR, 2)
void mlp_kernel(const float* __restrict__ p, const float* __restrict__ c,
                const float* __restrict__ fc_p_W, const float* __restrict__ fc_p_b,
                const float* __restrict__ fc_c_W,
                const float* __restrict__ blk0_W, const float* __restrict__ blk0_b,
                const float* __restrict__ blk1_W, const float* __restrict__ blk1_b,
                const float* __restrict__ fc_out_W, const float* __restrict__ fc_out_b,
                float* __restrict__ out) {
    extern __shared__ float sm[];
    const int tid = threadIdx.x;
    const int og  = tid & 7;          // cols og*4..+3 and 32+og*4..+3
    const int pg  = tid >> 3;         // rows pg + 16q, q=0..7
    const int base = blockIdx.x * PTS;
    const int bA_id = base / NPTS;
    const int bB_id = (base + PTS - 1) / NPTS;

    float* WA   = sm + OFF_WA;
    float* WB   = sm + OFF_WB;
    float* NETB = sm + OFF_NET;
    float* X    = sm + OFF_X;

    // prologue async: Wc_0 -> WA (group), codes -> X (group)
    load_w16(WA, fc_c_W, tid); cpa_commit();
    load_codes(X, c + (size_t)base * 64, tid); cpa_commit();

    // one-time small operands -> smem (strided over full range; THR=128)
    for (int w = tid; w < 768; w += THR) sm[OFF_OW + w] = fc_out_W[w];
    if (tid < 16) sm[OFF_OB + tid] = (tid < 12) ? fc_out_b[tid] : 0.f;
    for (int w = tid; w < 192; w += THR) sm[OFF_PW + w] = fc_p_W[w];
    for (int w = tid; w < 64; w += THR) sm[OFF_PB + w] = fc_p_b[w];
    for (int w = tid; w < 640; w += THR) {          // cond rows for batches bA/bB
        int sel = w / 320, r = w % 320;
        sm[OFF_CND + w] = g_cond[(sel ? bB_id : bA_id) * 320 + r];
    }
    for (int w = tid; w < 320; w += THR) {
        sm[OFF_B0 + w] = blk0_b[w];
        sm[OFF_B1 + w] = blk1_b[w];
    }
    __syncthreads();   // smem params visible (cp.async groups still in flight)

    float* wrN = NETB + pg * XSTR + og * 4;      // own net tile
    float* wrX = X    + pg * XSTR + og * 4;      // own h tile
    const float* xb = X    + pg * XSTR;
    const float* nb = NETB + pg * XSTR;

    // per-row cond smem offsets
    int cnd[8];
    #pragma unroll
    for (int q = 0; q < 8; q++) {
        int sel = ((base + pg + q * 16) / NPTS == bB_id) ? 1 : 0;
        cnd[q] = OFF_CND + sel * 320 + og * 4;
    }

    // ---- p-layer: net0 = p @ Wp + bp -> NETB (own tile) ----
    {
        ulonglong2 bA = *(const ulonglong2*)(sm + OFF_PB + og * 4);
        ulonglong2 bB = *(const ulonglong2*)(sm + OFF_PB + og * 4 + 32);
        ulonglong2 w[3][2];
        #pragma unroll
        for (int e = 0; e < 3; e++) {
            w[e][0] = *(const ulonglong2*)(sm + OFF_PW + e * 64 + og * 4);
            w[e][1] = *(const ulonglong2*)(sm + OFF_PW + e * 64 + og * 4 + 32);
        }
        #pragma unroll
        for (int q = 0; q < 8; q++) {
            int pt = base + pg + q * 16;
            ull a0 = bA.x, a1 = bA.y, a2 = bB.x, a3 = bB.y;
            #pragma unroll
            for (int e = 0; e < 3; e++) {
                ull xd = dup2(__ldg(p + (size_t)pt * 3 + e));
                fma2(a0, xd, w[e][0].x); fma2(a1, xd, w[e][0].y);
                fma2(a2, xd, w[e][1].x); fma2(a3, xd, w[e][1].y);
            }
            ulonglong2 s0, s1; s0.x = a0; s0.y = a1; s1.x = a2; s1.y = a3;
            *(ulonglong2*)(wrN + q * 16 * XSTR)      = s0;
            *(ulonglong2*)(wrN + q * 16 * XSTR + 32) = s1;
        }
    }

    for (int i = 0; i < NBLK; i++) {
        float* Wcur = (i & 1) ? WB : WA;
        float* Woth = (i & 1) ? WA : WB;

        if (i > 0) { load_codes(X, c + (size_t)base * 64, tid); cpa_commit(); }
        load_w16(Woth, blk0_W + (size_t)i * 4096, tid); cpa_commit();
        cpa_wait<1>();            // Wc_i + codes done; W0 still in flight
        __syncthreads();

        ull acc[8][4];
        // ---- step1: net = net + cond + c @ Wc ----
        #pragma unroll
        for (int q = 0; q < 8; q++) {
            ulonglong2 a = *(const ulonglong2*)(wrN + q * 16 * XSTR);
            ulonglong2 b = *(const ulonglong2*)(wrN + q * 16 * XSTR + 32);
            ulonglong2 c0 = *(const ulonglong2*)(sm + cnd[q] + i * 64);
            ulonglong2 c1 = *(const ulonglong2*)(sm + cnd[q] + i * 64 + 32);
            acc[q][0] = a.x; acc[q][1] = a.y; acc[q][2] = b.x; acc[q][3] = b.y;
            add2(acc[q][0], c0.x); add2(acc[q][1], c0.y);
            add2(acc[q][2], c1.x); add2(acc[q][3], c1.y);
        }
        mm64(acc, xb, Wcur + og * 4, false);
        #pragma unroll
        for (int q = 0; q < 8; q++) {
            ulonglong2 s0, s1;
            s0.x = acc[q][0]; s0.y = acc[q][1]; s1.x = acc[q][2]; s1.y = acc[q][3];
            *(ulonglong2*)(wrN + q * 16 * XSTR)      = s0;
            *(ulonglong2*)(wrN + q * 16 * XSTR + 32) = s1;
        }
        cpa_wait<0>();            // W0 arrived
        __syncthreads();

        // ---- step2: h = relu(net) @ W0 + b0 ; relu(h) -> X ----
        load_w16(Wcur, blk1_W + (size_t)i * 4096, tid); cpa_commit();  // W1 prefetch
        {
            ulonglong2 bA = *(const ulonglong2*)(sm + OFF_B0 + i * 64 + og * 4);
            ulonglong2 bB = *(const ulonglong2*)(sm + OFF_B0 + i * 64 + og * 4 + 32);
            #pragma unroll
            for (int q = 0; q < 8; q++) {
                acc[q][0] = bA.x; acc[q][1] = bA.y; acc[q][2] = bB.x; acc[q][3] = bB.y;
            }
            mm64(acc, nb, Woth + og * 4, true);
            #pragma unroll
            for (int q = 0; q < 8; q++) {
                float2 f0 = unpk(acc[q][0]), f1 = unpk(acc[q][1]);
                float2 f2 = unpk(acc[q][2]), f3 = unpk(acc[q][3]);
                *(float4*)(wrX + q * 16 * XSTR) =
                    make_float4(fmaxf(f0.x, 0.f), fmaxf(f0.y, 0.f),
                                fmaxf(f1.x, 0.f), fmaxf(f1.y, 0.f));
                *(float4*)(wrX + q * 16 * XSTR + 32) =
                    make_float4(fmaxf(f2.x, 0.f), fmaxf(f2.y, 0.f),
                                fmaxf(f3.x, 0.f), fmaxf(f3.y, 0.f));
            }
        }
        cpa_wait<0>();            // W1 arrived
        __syncthreads();

        // ---- step3: net += relu(h) @ W1 + b1 ----
        if (i < NBLK - 1) { load_w16(Woth, fc_c_W + (size_t)(i + 1) * 576 * 64, tid); cpa_commit(); }
        {
            ulonglong2 bA = *(const ulonglong2*)(sm + OFF_B1 + i * 64 + og * 4);
            ulonglong2 bB = *(const ulonglong2*)(sm + OFF_B1 + i * 64 + og * 4 + 32);
            #pragma unroll
            for (int q = 0; q < 8; q++) {
                ulonglong2 a = *(const ulonglong2*)(wrN + q * 16 * XSTR);
                ulonglong2 b = *(const ulonglong2*)(wrN + q * 16 * XSTR + 32);
                acc[q][0] = a.x; acc[q][1] = a.y; acc[q][2] = b.x; acc[q][3] = b.y;
                add2(acc[q][0], bA.x); add2(acc[q][1], bA.y);
                add2(acc[q][2], bB.x); add2(acc[q][3], bB.y);
            }
            mm64(acc, xb, Wcur + og * 4, false);
            #pragma unroll
            for (int q = 0; q < 8; q++) {
                ulonglong2 s0, s1;
                s0.x = acc[q][0]; s0.y = acc[q][1]; s1.x = acc[q][2]; s1.y = acc[q][3];
                *(ulonglong2*)(wrN + q * 16 * XSTR)      = s0;
                *(ulonglong2*)(wrN + q * 16 * XSTR + 32) = s1;
            }
        }
        __syncthreads();
    }

    // ---- out = relu(net) @ fc_out_W + fc_out_b ; one point per thread ----
    {
        ull o[6];
        const ull* ob = (const ull*)(sm + OFF_OB);
        #pragma unroll
        for (int j = 0; j < 6; j++) o[j] = ob[j];
        const float* xr = NETB + tid * XSTR;
        #pragma unroll 2
        for (int kk = 0; kk < 64; kk += 4) {
            float xa[4];
            *(float4*)xa = *(const float4*)(xr + kk);
            #pragma unroll
            for (int d = 0; d < 4; d++) {
                ull xd = dup2(fmaxf(xa[d], 0.f));
                const ull* wr = (const ull*)(sm + OFF_OW + (kk + d) * 12);
                #pragma unroll
                for (int j = 0; j < 6; j++) fma2(o[j], xd, wr[j]);
            }
        }
        float2 f0 = unpk(o[0]), f1 = unpk(o[1]), f2 = unpk(o[2]);
        float2 f3 = unpk(o[3]), f4 = unpk(o[4]), f5 = unpk(o[5]);
        float4* dst = (float4*)(out + (size_t)(base + tid) * 12);
        dst[0] = make_float4(f0.x, f0.y, f1.x, f1.y);
        dst[1] = make_float4(f2.x, f2.y, f3.x, f3.y);
        dst[2] = make_float4(f4.x, f4.y, f5.x, f5.y);
    }
}

extern "C" void kernel_launch(void* const* d_in, const int* in_sizes, int n_in,
                              void* d_out, int out_size) {
    const float* p        = (const float*)d_in[0];
    const float* c        = (const float*)d_in[1];
    const float* tf       = (const float*)d_in[2];
    const float* fc_p_W   = (const float*)d_in[3];
    const float* fc_p_b   = (const float*)d_in[4];
    const float* fc_c_W   = (const float*)d_in[5];
    const float* fc_c_b   = (const float*)d_in[6];
    const float* blk0_W   = (const float*)d_in[7];
    const float* blk0_b   = (const float*)d_in[8];
    const float* blk1_W   = (const float*)d_in[9];
    const float* blk1_b   = (const float*)d_in[10];
    const float* fc_out_W = (const float*)d_in[11];
    const float* fc_out_b = (const float*)d_in[12];
    float* out = (float*)d_out;

    cudaFuncSetAttribute(mlp_kernel, cudaFuncAttributeMaxDynamicSharedMemorySize, SM_BYTES);

    cond_kernel<<<8 * NBLK, 256>>>(tf, fc_c_W, fc_c_b);

    int grid = TOT / PTS;   // 3125 CTAs
    mlp_kernel<<<grid, THR, SM_BYTES>>>(p, c, fc_p_W, fc_p_b, fc_c_W,
                                        blk0_W, blk0_b, blk1_W, blk1_b,
                                        fc_out_W, fc_out_b, out);
}

// round 16
// speedup vs baseline: 2.3617x; 2.3617x over previous
#include <cuda_runtime.h>
#include <cuda_bf16.h>
#include <cstdint>

#define TOT   400000
#define NPTS  50000
#define NBLK  5
#define PTS   128
#define THR   128
#define CSTR  72      // codes row stride (bf16)
#define NSTR  68      // final net row stride (f32)

__device__ float g_cond[8 * NBLK * 64];
__device__ float g_C[8][6][64];
__device__ uint2 g_Bf[15][2][1024];   // frag-packed weights: [mat][hi/lo][(kt*8+nt)*32+lane]

__device__ __forceinline__ uint32_t smem_u32(const void* p) { return (uint32_t)__cvta_generic_to_shared(p); }
__device__ __forceinline__ void cpa16(uint32_t d, const void* s) {
    asm volatile("cp.async.cg.shared.global [%0], [%1], 16;" :: "r"(d), "l"(s));
}
__device__ __forceinline__ void cpa_commit() { asm volatile("cp.async.commit_group;"); }
template<int N> __device__ __forceinline__ void cpa_wait() { asm volatile("cp.async.wait_group %0;" :: "n"(N)); }

__device__ __forceinline__ void mmabf(float c[4], const uint32_t a[4], uint2 b) {
    asm volatile("mma.sync.aligned.m16n8k16.row.col.f32.bf16.bf16.f32 "
        "{%0,%1,%2,%3}, {%4,%5,%6,%7}, {%8,%9}, {%0,%1,%2,%3};"
        : "+f"(c[0]), "+f"(c[1]), "+f"(c[2]), "+f"(c[3])
        : "r"(a[0]), "r"(a[1]), "r"(a[2]), "r"(a[3]), "r"(b.x), "r"(b.y));
}
__device__ __forceinline__ void ldsm4(uint32_t r[4], uint32_t addr) {
    asm volatile("ldmatrix.sync.aligned.m8n8.x4.shared.b16 {%0,%1,%2,%3}, [%4];"
        : "=r"(r[0]), "=r"(r[1]), "=r"(r[2]), "=r"(r[3]) : "r"(addr));
}
__host__ __device__ __forceinline__ void cvt2(float v0, float v1, uint32_t& hi, uint32_t& lo) {
    __nv_bfloat162 h = __floats2bfloat162_rn(v0, v1);
    __nv_bfloat162 l = __floats2bfloat162_rn(v0 - __bfloat162float(h.x), v1 - __bfloat162float(h.y));
    hi = *(uint32_t*)&h; lo = *(uint32_t*)&l;
}

// ---------------- shared layout (bytes) ----------------
#define SB_CODES_H 0        // 128*72*2 = 18432
#define SB_CODES_L 18432    // -> 36864
#define SB_NETF    0        // final f32 acts (aliases codes; used only after last codes read)
#define SB_B0      36864    // 16384 (hi 8KB + lo 8KB)
#define SB_B1      53248    // 16384
#define SB_OW      69632    // 768 f32
#define SB_OB      72704    // 16 f32
#define SB_CT      72768    // 768 f32 (2 batches x 6 x 64)
#define SB_B0T     75840    // 320 f32
#define SB_PW      77120    // 192 f32
#define SB_TOTAL   77888

// ---------------- prologue kernels ----------------
__global__ void cond_kernel(const float* __restrict__ tf, const float* __restrict__ fc_c_W,
                            const float* __restrict__ fc_c_b) {
    int bi = blockIdx.x, b = bi / NBLK, i = bi % NBLK;
    int h = threadIdx.x & 63, g = threadIdx.x >> 6;
    const float* W = fc_c_W + (size_t)i * 576 * 64 + 64 * 64 + h;
    const float* t = tf + b * 512;
    float acc = 0.f;
    int k0 = g * 128;
    #pragma unroll 8
    for (int k = k0; k < k0 + 128; k++) acc += t[k] * W[(size_t)k * 64];
    __shared__ float red[256];
    red[threadIdx.x] = acc;
    __syncthreads();
    if (g == 0)
        g_cond[bi * 64 + h] = red[h] + red[h + 64] + red[h + 128] + red[h + 192] + fc_c_b[i * 64 + h];
}

__global__ void corr_kernel(const float* __restrict__ fc_p_b, const float* __restrict__ blk1_b) {
    int b = blockIdx.x, h = threadIdx.x;
    float cum = fc_p_b[h];
    #pragma unroll
    for (int i = 0; i < NBLK; i++) {
        cum += g_cond[(b * NBLK + i) * 64 + h];
        g_C[b][i][h] = cum;
        cum += blk1_b[i * 64 + h];
    }
    g_C[b][5][h] = cum;
}

// pack W (64x64, y = x@W) into mma B-fragment layout, hi/lo split
__global__ void wpack_kernel(const float* __restrict__ fc_c_W, const float* __restrict__ blk0_W,
                             const float* __restrict__ blk1_W) {
    int m = blockIdx.x, i = m / 3, t = m % 3;
    const float* src = (t == 0) ? fc_c_W + (size_t)i * 576 * 64
                     : (t == 1) ? blk0_W + (size_t)i * 4096 : blk1_W + (size_t)i * 4096;
    for (int e = threadIdx.x; e < 1024; e += blockDim.x) {
        int lane = e & 31, frag = e >> 5;
        int kt = frag >> 3, nt = frag & 7;
        int k0 = kt * 16 + 2 * (lane & 3);
        int n  = nt * 8 + (lane >> 2);
        uint32_t h0, l0, h1, l1;
        cvt2(src[k0 * 64 + n], src[(k0 + 1) * 64 + n], h0, l0);
        cvt2(src[(k0 + 8) * 64 + n], src[(k0 + 9) * 64 + n], h1, l1);
        g_Bf[m][0][e] = make_uint2(h0, h1);
        g_Bf[m][1][e] = make_uint2(l0, l1);
    }
}

// ---------------- main kernel ----------------
__device__ __forceinline__ void load_Bm(char* smc, int slot, const uint2* src, int tid) {
    uint32_t d = smem_u32(smc + slot);
    const char* s = (const char*)src;
    #pragma unroll
    for (int t = 0; t < 8; t++) cpa16(d + tid * 16 + t * 2048, s + tid * 16 + t * 2048);
}

// build A frags (hi/lo) for k-tile kt from C frags + per-row corrections + relu
__device__ __forceinline__ void build_A(const float cfr[8][4], const float* ctA, const float* ctB,
                                        int colb, int kt, uint32_t Ah[4], uint32_t Al[4]) {
    int jA = 2 * kt, jB = 2 * kt + 1;
    float2 a0 = *(const float2*)(ctA + jA * 8 + colb);
    float2 b0 = *(const float2*)(ctB + jA * 8 + colb);
    float2 a1 = *(const float2*)(ctA + jB * 8 + colb);
    float2 b1 = *(const float2*)(ctB + jB * 8 + colb);
    cvt2(fmaxf(cfr[jA][0] + a0.x, 0.f), fmaxf(cfr[jA][1] + a0.y, 0.f), Ah[0], Al[0]);
    cvt2(fmaxf(cfr[jA][2] + b0.x, 0.f), fmaxf(cfr[jA][3] + b0.y, 0.f), Ah[1], Al[1]);
    cvt2(fmaxf(cfr[jB][0] + a1.x, 0.f), fmaxf(cfr[jB][1] + a1.y, 0.f), Ah[2], Al[2]);
    cvt2(fmaxf(cfr[jB][2] + b1.x, 0.f), fmaxf(cfr[jB][3] + b1.y, 0.f), Ah[3], Al[3]);
}

__global__ void __launch_bounds__(THR, 2)
mlp_kernel(const float* __restrict__ p, const float* __restrict__ c,
           const float* __restrict__ fc_p_W, const float* __restrict__ blk0_b,
           const float* __restrict__ fc_out_W, const float* __restrict__ fc_out_b,
           float* __restrict__ out) {
    extern __shared__ char smc[];
    float* smf = (float*)smc;
    const int tid = threadIdx.x, lane = tid & 31, warp = tid >> 5;
    const int base = blockIdx.x * PTS;
    const int bA = base / NPTS, bB = (base + PTS - 1) / NPTS;
    const int colb = 2 * (lane & 3);
    const int mbase = warp * 32;

    load_Bm(smc, SB_B0, &g_Bf[0][0][0], tid);   // Wc_0
    cpa_commit();

    for (int w = tid; w < 768; w += THR) smf[SB_OW / 4 + w] = fc_out_W[w];
    if (tid < 16) smf[SB_OB / 4 + tid] = (tid < 12) ? fc_out_b[tid] : 0.f;
    for (int w = tid; w < 768; w += THR) {
        int s2 = w / 384, r2 = w % 384;
        smf[SB_CT / 4 + w] = (&g_C[0][0][0])[(s2 ? bB : bA) * 384 + r2];
    }
    for (int w = tid; w < 320; w += THR) smf[SB_B0T / 4 + w] = blk0_b[w];
    for (int w = tid; w < 192; w += THR) smf[SB_PW / 4 + w] = fc_p_W[w];

    // codes -> bf16 hi/lo (plain [row][k], stride CSTR)
    for (int e = tid; e < PTS * 64; e += THR) {
        int row = e >> 6, col = e & 63;
        uint32_t hi, lo;
        float v = c[(size_t)(base + row) * 64 + col];
        cvt2(v, 0.f, hi, lo);
        *(__nv_bfloat16*)(smc + SB_CODES_H + (row * CSTR + col) * 2) = ((__nv_bfloat162*)&hi)->x;
        *(__nv_bfloat16*)(smc + SB_CODES_L + (row * CSTR + col) * 2) = ((__nv_bfloat162*)&lo)->x;
    }

    // per-row correction-table pointers (batch-dependent)
    const float* ctp[2][2];
    #pragma unroll
    for (int mt = 0; mt < 2; mt++) {
        int r1 = mbase + mt * 16 + (lane >> 2);
        ctp[mt][0] = smf + SB_CT / 4 + (((base + r1) / NPTS == bB) ? 384 : 0);
        ctp[mt][1] = smf + SB_CT / 4 + (((base + r1 + 8) / NPTS == bB) ? 384 : 0);
    }

    // p-layer -> net C-fragments (raw, bias folded into g_C)
    float net[2][8][4], hbuf[2][8][4];
    #pragma unroll
    for (int mt = 0; mt < 2; mt++) {
        int r1 = mbase + mt * 16 + (lane >> 2);
        float pv1[3], pv2[3];
        #pragma unroll
        for (int e = 0; e < 3; e++) {
            pv1[e] = __ldg(p + (size_t)(base + r1) * 3 + e);
            pv2[e] = __ldg(p + (size_t)(base + r1 + 8) * 3 + e);
        }
        #pragma unroll
        for (int j = 0; j < 8; j++) {
            int colA = j * 8 + colb;
            float2 w0 = *(const float2*)(smf + SB_PW / 4 + colA);
            float2 w1 = *(const float2*)(smf + SB_PW / 4 + 64 + colA);
            float2 w2 = *(const float2*)(smf + SB_PW / 4 + 128 + colA);
            net[mt][j][0] = pv1[0] * w0.x + pv1[1] * w1.x + pv1[2] * w2.x;
            net[mt][j][1] = pv1[0] * w0.y + pv1[1] * w1.y + pv1[2] * w2.y;
            net[mt][j][2] = pv2[0] * w0.x + pv2[1] * w1.x + pv2[2] * w2.x;
            net[mt][j][3] = pv2[0] * w0.y + pv2[1] * w1.y + pv2[2] * w2.y;
        }
    }

    for (int s = 0; s < 15; s++) {
        int step = s % 3, i = s / 3;
        int slot = (s & 1) ? SB_B1 : SB_B0;
        int oth  = (s & 1) ? SB_B0 : SB_B1;

        __syncthreads();                       // everyone done reading 'oth' (step s-1)
        if (s + 1 < 15) { load_Bm(smc, oth, &g_Bf[s + 1][0][0], tid); cpa_commit(); }
        if (s + 1 < 15) cpa_wait<1>(); else cpa_wait<0>();
        __syncthreads();                       // slot s data visible to all

        if (step == 0) {
            // net += codes @ Wc_i  (A via ldmatrix, 3 terms)
            #pragma unroll
            for (int kt = 0; kt < 4; kt++) {
                uint32_t Ah[2][4], Al[2][4];
                #pragma unroll
                for (int mt = 0; mt < 2; mt++) {
                    int row = mbase + mt * 16 + ((lane >> 3) & 1) * 8 + (lane & 7);
                    int kc  = kt * 16 + (lane >> 4) * 8;
                    ldsm4(Ah[mt], smem_u32(smc + SB_CODES_H + (row * CSTR + kc) * 2));
                    ldsm4(Al[mt], smem_u32(smc + SB_CODES_L + (row * CSTR + kc) * 2));
                }
                #pragma unroll
                for (int nt = 0; nt < 8; nt++) {
                    uint2 bh = *(const uint2*)(smc + slot + ((kt * 8 + nt) * 32 + lane) * 8);
                    uint2 bl = *(const uint2*)(smc + slot + 8192 + ((kt * 8 + nt) * 32 + lane) * 8);
                    #pragma unroll
                    for (int mt = 0; mt < 2; mt++) {
                        mmabf(net[mt][nt], Ah[mt], bh);
                        mmabf(net[mt][nt], Ah[mt], bl);
                        mmabf(net[mt][nt], Al[mt], bh);
                    }
                }
            }
        } else if (step == 1) {
            // h = relu(net + C[i]) @ W0_i
            #pragma unroll
            for (int mt = 0; mt < 2; mt++)
                #pragma unroll
                for (int j = 0; j < 8; j++)
                    #pragma unroll
                    for (int q = 0; q < 4; q++) hbuf[mt][j][q] = 0.f;
            #pragma unroll
            for (int kt = 0; kt < 4; kt++) {
                uint32_t Ah[2][4], Al[2][4];
                #pragma unroll
                for (int mt = 0; mt < 2; mt++)
                    build_A(net[mt], ctp[mt][0] + i * 64, ctp[mt][1] + i * 64, colb, kt, Ah[mt], Al[mt]);
                #pragma unroll
                for (int nt = 0; nt < 8; nt++) {
                    uint2 bh = *(const uint2*)(smc + slot + ((kt * 8 + nt) * 32 + lane) * 8);
                    uint2 bl = *(const uint2*)(smc + slot + 8192 + ((kt * 8 + nt) * 32 + lane) * 8);
                    #pragma unroll
                    for (int mt = 0; mt < 2; mt++) {
                        mmabf(hbuf[mt][nt], Ah[mt], bh);
                        mmabf(hbuf[mt][nt], Ah[mt], bl);
                        mmabf(hbuf[mt][nt], Al[mt], bh);
                    }
                }
            }
        } else {
            // net += relu(h + b0_i) @ W1_i   (b1 folded into C)
            const float* bp = smf + SB_B0T / 4 + i * 64;
            #pragma unroll
            for (int kt = 0; kt < 4; kt++) {
                uint32_t Ah[2][4], Al[2][4];
                #pragma unroll
                for (int mt = 0; mt < 2; mt++)
                    build_A(hbuf[mt], bp, bp, colb, kt, Ah[mt], Al[mt]);
                #pragma unroll
                for (int nt = 0; nt < 8; nt++) {
                    uint2 bh = *(const uint2*)(smc + slot + ((kt * 8 + nt) * 32 + lane) * 8);
                    uint2 bl = *(const uint2*)(smc + slot + 8192 + ((kt * 8 + nt) * 32 + lane) * 8);
                    #pragma unroll
                    for (int mt = 0; mt < 2; mt++) {
                        mmabf(net[mt][nt], Ah[mt], bh);
                        mmabf(net[mt][nt], Ah[mt], bl);
                        mmabf(net[mt][nt], Al[mt], bh);
                    }
                }
            }
        }
    }

    // final activations relu(net + C5) -> smem f32 (aliases codes region; safe now)
    __syncthreads();
    #pragma unroll
    for (int mt = 0; mt < 2; mt++) {
        int r1 = mbase + mt * 16 + (lane >> 2);
        #pragma unroll
        for (int j = 0; j < 8; j++) {
            int colA = j * 8 + colb;
            float2 cA = *(const float2*)(ctp[mt][0] + 5 * 64 + colA);
            float2 cB = *(const float2*)(ctp[mt][1] + 5 * 64 + colA);
            *(float2*)(smf + SB_NETF / 4 + r1 * NSTR + colA) =
                make_float2(fmaxf(net[mt][j][0] + cA.x, 0.f), fmaxf(net[mt][j][1] + cA.y, 0.f));
            *(float2*)(smf + SB_NETF / 4 + (r1 + 8) * NSTR + colA) =
                make_float2(fmaxf(net[mt][j][2] + cB.x, 0.f), fmaxf(net[mt][j][3] + cB.y, 0.f));
        }
    }
    __syncthreads();

    // out = act @ Wout + bout ; one point per thread
    {
        float o[12];
        #pragma unroll
        for (int j = 0; j < 12; j++) o[j] = smf[SB_OB / 4 + j];
        const float* xr = smf + SB_NETF / 4 + tid * NSTR;
        #pragma unroll 8
        for (int cc = 0; cc < 64; cc++) {
            float v = xr[cc];
            #pragma unroll
            for (int j = 0; j < 12; j++) o[j] += v * smf[SB_OW / 4 + cc * 12 + j];
        }
        float4* dst = (float4*)(out + (size_t)(base + tid) * 12);
        dst[0] = make_float4(o[0], o[1], o[2], o[3]);
        dst[1] = make_float4(o[4], o[5], o[6], o[7]);
        dst[2] = make_float4(o[8], o[9], o[10], o[11]);
    }
}

extern "C" void kernel_launch(void* const* d_in, const int* in_sizes, int n_in,
                              void* d_out, int out_size) {
    const float* p        = (const float*)d_in[0];
    const float* c        = (const float*)d_in[1];
    const float* tf       = (const float*)d_in[2];
    const float* fc_p_W   = (const float*)d_in[3];
    const float* fc_p_b   = (const float*)d_in[4];
    const float* fc_c_W   = (const float*)d_in[5];
    const float* fc_c_b   = (const float*)d_in[6];
    const float* blk0_W   = (const float*)d_in[7];
    const float* blk0_b   = (const float*)d_in[8];
    const float* blk1_W   = (const float*)d_in[9];
    const float* blk1_b   = (const float*)d_in[10];
    const float* fc_out_W = (const float*)d_in[11];
    const float* fc_out_b = (const float*)d_in[12];
    float* out = (float*)d_out;

    cudaFuncSetAttribute(mlp_kernel, cudaFuncAttributeMaxDynamicSharedMemorySize, SB_TOTAL);

    cond_kernel<<<8 * NBLK, 256>>>(tf, fc_c_W, fc_c_b);
    corr_kernel<<<8, 64>>>(fc_p_b, blk1_b);
    wpack_kernel<<<15, 256>>>(fc_c_W, blk0_W, blk1_W);

    mlp_kernel<<<TOT / PTS, THR, SB_TOTAL>>>(p, c, fc_p_W, blk0_b, fc_out_W, fc_out_b, out);
}